// round 3
// baseline (speedup 1.0000x reference)
#include <cuda_runtime.h>
#include <math.h>

// Problem constants
#define B_    8
#define S_    2048
#define D_    512
#define NROWS (B_ * S_)      // 16384

// GEMM tiling
#define BM 128
#define BN 128
#define BK 16

typedef unsigned long long u64;

// Scratch (static device globals — no runtime allocation)
__device__ float g_q[(size_t)NROWS * D_];
__device__ float g_k[(size_t)NROWS * D_];
__device__ float g_v[(size_t)NROWS * D_];
__device__ float g_y[(size_t)NROWS * D_];
__device__ float g_s[(size_t)B_ * S_ * S_];   // 134 MB scores/attn

// ---------------------------------------------------------------------------
// Shared GEMM body.
//   C[m,n] = alpha * sum_k A[m,k] * B(n,k)  (+ bias[n])
//   TRANS_B = true : B is row-major [N,K]   (C = A * B^T)   — QKV, scores, out
//   TRANS_B = false: B is row-major [K,N]   (C = A * B)     — attn*V
//   ADD_POS: A[m,k] += pos[(m % S_) * D_ + k]  (only used when K == D_)
// M % BM == 0, N % BN == 0, K % BK == 0 for all call sites (checked statically
// by the launch configs below).
// ---------------------------------------------------------------------------
template <bool TRANS_B, bool ADD_POS, bool HAS_BIAS>
__device__ __forceinline__ void gemm_body(
    const float* __restrict__ A, const float* __restrict__ Bm,
    const float* __restrict__ bias, const float* __restrict__ pos,
    float* __restrict__ C, int M, int N, int K, float alpha,
    int bm, int bn)
{
    __shared__ float As[BK][BM + 4];
    __shared__ float Bs[BK][BN + 4];

    const int tid = threadIdx.x;      // 0..255
    const int tx  = tid & 15;         // col group
    const int ty  = tid >> 4;         // row group

    float4 aReg[2], bReg[2];

    // Global -> register fetch for k-tile t
    auto gload = [&](int t) {
        const int k0 = t * BK;
#pragma unroll
        for (int L = 0; L < 2; ++L) {
            const int vv   = tid + L * 256;        // float4 index within tile
            const int arow = vv >> 2;              // 0..127
            const int ac4  = vv & 3;               // 0..3  (BK/4)
            const int m    = bm * BM + arow;
            float4 f = *reinterpret_cast<const float4*>(
                &A[(size_t)m * K + k0 + ac4 * 4]);
            if constexpr (ADD_POS) {
                const float4 pz = *reinterpret_cast<const float4*>(
                    &pos[(size_t)(m & (S_ - 1)) * D_ + k0 + ac4 * 4]);
                f.x += pz.x; f.y += pz.y; f.z += pz.z; f.w += pz.w;
            }
            aReg[L] = f;
            if constexpr (TRANS_B) {
                bReg[L] = *reinterpret_cast<const float4*>(
                    &Bm[(size_t)(bn * BN + arow) * K + k0 + ac4 * 4]);
            } else {
                const int brow = vv >> 5;          // 0..15
                const int bc4  = vv & 31;          // 0..31 (BN/4)
                bReg[L] = *reinterpret_cast<const float4*>(
                    &Bm[(size_t)(k0 + brow) * N + bn * BN + bc4 * 4]);
            }
        }
    };

    // Register -> shared store
    auto sstore = [&]() {
#pragma unroll
        for (int L = 0; L < 2; ++L) {
            const int vv   = tid + L * 256;
            const int arow = vv >> 2;
            const int ac4  = vv & 3;
            As[ac4 * 4 + 0][arow] = aReg[L].x;
            As[ac4 * 4 + 1][arow] = aReg[L].y;
            As[ac4 * 4 + 2][arow] = aReg[L].z;
            As[ac4 * 4 + 3][arow] = aReg[L].w;
            if constexpr (TRANS_B) {
                Bs[ac4 * 4 + 0][arow] = bReg[L].x;
                Bs[ac4 * 4 + 1][arow] = bReg[L].y;
                Bs[ac4 * 4 + 2][arow] = bReg[L].z;
                Bs[ac4 * 4 + 3][arow] = bReg[L].w;
            } else {
                const int brow = vv >> 5;
                const int bc4  = vv & 31;
                *reinterpret_cast<float4*>(&Bs[brow][bc4 * 4]) = bReg[L];
            }
        }
    };

    // Packed f32x2 accumulators: acc2[i][j] holds columns (2j, 2j+1) of row i
    u64 acc2[8][4];
#pragma unroll
    for (int i = 0; i < 8; ++i)
#pragma unroll
        for (int j = 0; j < 4; ++j) acc2[i][j] = 0ULL;   // = {+0.f, +0.f}

    const int ktiles = K / BK;
    gload(0);
    sstore();
    __syncthreads();

    for (int t = 0; t < ktiles; ++t) {
        const bool nxt = (t + 1 < ktiles);
        if (nxt) gload(t + 1);

#pragma unroll
        for (int kk = 0; kk < BK; ++kk) {
            const float4 a0 = *reinterpret_cast<const float4*>(&As[kk][ty * 8]);
            const float4 a1 = *reinterpret_cast<const float4*>(&As[kk][ty * 8 + 4]);
            const ulonglong2 q0 = *reinterpret_cast<const ulonglong2*>(&Bs[kk][tx * 8]);
            const ulonglong2 q1 = *reinterpret_cast<const ulonglong2*>(&Bs[kk][tx * 8 + 4]);
            const u64 b2[4] = {q0.x, q0.y, q1.x, q1.y};
            const float av[8] = {a0.x, a0.y, a0.z, a0.w, a1.x, a1.y, a1.z, a1.w};
#pragma unroll
            for (int i = 0; i < 8; ++i) {
                u64 asp;
                asm("mov.b64 %0, {%1, %1};" : "=l"(asp) : "f"(av[i]));
#pragma unroll
                for (int j = 0; j < 4; ++j)
                    asm("fma.rn.f32x2 %0, %1, %2, %0;"
                        : "+l"(acc2[i][j]) : "l"(asp), "l"(b2[j]));
            }
        }
        __syncthreads();
        if (nxt) { sstore(); __syncthreads(); }
    }

    // Epilogue
    const int row0 = bm * BM + ty * 8;
    const int col0 = bn * BN + tx * 8;
#pragma unroll
    for (int i = 0; i < 8; ++i) {
        float o[8];
#pragma unroll
        for (int j = 0; j < 4; ++j)
            asm("mov.b64 {%0, %1}, %2;"
                : "=f"(o[2 * j]), "=f"(o[2 * j + 1]) : "l"(acc2[i][j]));
#pragma unroll
        for (int c = 0; c < 8; ++c) {
            o[c] *= alpha;
            if constexpr (HAS_BIAS) o[c] += bias[col0 + c];
        }
        *reinterpret_cast<float4*>(&C[(size_t)(row0 + i) * N + col0]) =
            make_float4(o[0], o[1], o[2], o[3]);
        *reinterpret_cast<float4*>(&C[(size_t)(row0 + i) * N + col0 + 4]) =
            make_float4(o[4], o[5], o[6], o[7]);
    }
}

// ---------------------------------------------------------------------------
// Kernels
// ---------------------------------------------------------------------------

// Fused pos-add + Q/K/V projection. blockIdx.z selects {Wq,bq,q}/{Wk,bk,k}/{Wv,bv,v}.
__global__ void __launch_bounds__(256) k_qkv(
    const float* __restrict__ x, const float* __restrict__ pos,
    const float* __restrict__ Wq, const float* __restrict__ bq,
    const float* __restrict__ Wk, const float* __restrict__ bk,
    const float* __restrict__ Wv, const float* __restrict__ bv,
    float* __restrict__ q, float* __restrict__ k, float* __restrict__ v)
{
    const float* W; const float* bb; float* o;
    if (blockIdx.z == 0)      { W = Wq; bb = bq; o = q; }
    else if (blockIdx.z == 1) { W = Wk; bb = bk; o = k; }
    else                      { W = Wv; bb = bv; o = v; }
    gemm_body<true, true, true>(x, W, bb, pos, o, NROWS, D_, D_, 1.0f,
                                blockIdx.y, blockIdx.x);
}

// scores[b] = (1/sqrt(D)) * q[b] @ k[b]^T
__global__ void __launch_bounds__(256) k_scores(
    const float* __restrict__ q, const float* __restrict__ k, float* __restrict__ s)
{
    const size_t b = blockIdx.z;
    gemm_body<true, false, false>(q + b * (size_t)S_ * D_, k + b * (size_t)S_ * D_,
                                  nullptr, nullptr, s + b * (size_t)S_ * S_,
                                  S_, S_, D_, 0.04419417382415922f,
                                  blockIdx.y, blockIdx.x);
}

// Row softmax over 2048 elements, in place. One CTA per row.
__global__ void __launch_bounds__(256) k_softmax(float* __restrict__ sc)
{
    float* p = sc + (size_t)blockIdx.x * S_;
    const int tid = threadIdx.x;
    __shared__ float red[8];

    float v[8];
    float mx = -3.4e38f;
#pragma unroll
    for (int i = 0; i < 8; ++i) { v[i] = p[tid + 256 * i]; mx = fmaxf(mx, v[i]); }
#pragma unroll
    for (int o = 16; o > 0; o >>= 1)
        mx = fmaxf(mx, __shfl_xor_sync(0xffffffffu, mx, o));
    if ((tid & 31) == 0) red[tid >> 5] = mx;
    __syncthreads();
    mx = red[0];
#pragma unroll
    for (int w = 1; w < 8; ++w) mx = fmaxf(mx, red[w]);

    float sum = 0.f;
#pragma unroll
    for (int i = 0; i < 8; ++i) { v[i] = expf(v[i] - mx); sum += v[i]; }
#pragma unroll
    for (int o = 16; o > 0; o >>= 1)
        sum += __shfl_xor_sync(0xffffffffu, sum, o);
    __syncthreads();               // red reuse: everyone done reading maxes
    if ((tid & 31) == 0) red[tid >> 5] = sum;
    __syncthreads();
    float tot = 0.f;
#pragma unroll
    for (int w = 0; w < 8; ++w) tot += red[w];
    const float inv = 1.0f / tot;
#pragma unroll
    for (int i = 0; i < 8; ++i) p[tid + 256 * i] = v[i] * inv;
}

// y[b] = attn[b] @ v[b]   (NN gemm)
__global__ void __launch_bounds__(256) k_av(
    const float* __restrict__ s, const float* __restrict__ v, float* __restrict__ y)
{
    const size_t b = blockIdx.z;
    gemm_body<false, false, false>(s + b * (size_t)S_ * S_, v + b * (size_t)S_ * D_,
                                   nullptr, nullptr, y + b * (size_t)S_ * D_,
                                   S_, D_, S_, 1.0f, blockIdx.y, blockIdx.x);
}

// out = y @ Wd^T + bd
__global__ void __launch_bounds__(256) k_out(
    const float* __restrict__ y, const float* __restrict__ Wd,
    const float* __restrict__ bd, float* __restrict__ o)
{
    gemm_body<true, false, true>(y, Wd, bd, nullptr, o, NROWS, D_, D_, 1.0f,
                                 blockIdx.y, blockIdx.x);
}

// ---------------------------------------------------------------------------
// Launch
// ---------------------------------------------------------------------------
extern "C" void kernel_launch(void* const* d_in, const int* in_sizes, int n_in,
                              void* d_out, int out_size)
{
    const float* x   = (const float*)d_in[0];
    const float* pos = (const float*)d_in[1];
    const float* Wq  = (const float*)d_in[2];
    const float* bq  = (const float*)d_in[3];
    const float* Wk  = (const float*)d_in[4];
    const float* bk  = (const float*)d_in[5];
    const float* Wv  = (const float*)d_in[6];
    const float* bv  = (const float*)d_in[7];
    const float* Wd  = (const float*)d_in[8];
    const float* bd  = (const float*)d_in[9];
    float* out = (float*)d_out;

    float *q, *k, *v, *y, *s;
    cudaGetSymbolAddress((void**)&q, g_q);
    cudaGetSymbolAddress((void**)&k, g_k);
    cudaGetSymbolAddress((void**)&v, g_v);
    cudaGetSymbolAddress((void**)&y, g_y);
    cudaGetSymbolAddress((void**)&s, g_s);

    k_qkv    <<<dim3(D_ / BN, NROWS / BM, 3), 256>>>(x, pos, Wq, bq, Wk, bk, Wv, bv, q, k, v);
    k_scores <<<dim3(S_ / BN, S_ / BM, B_),   256>>>(q, k, s);
    k_softmax<<<dim3(B_ * S_),                256>>>(s);
    k_av     <<<dim3(D_ / BN, S_ / BM, B_),   256>>>(s, v, y);
    k_out    <<<dim3(D_ / BN, NROWS / BM, 1), 256>>>(y, Wd, bd, out);
}

// round 5
// speedup vs baseline: 2.3932x; 2.3932x over previous
#include <cuda_runtime.h>
#include <cuda_bf16.h>
#include <stdint.h>

typedef unsigned int u32;

#define B_    8
#define S_    2048
#define D_    512
#define NROWS 16384

// Tiling
#define TM 128
#define TN 128
#define TK 32

// SMEM layout (bytes)
#define A_STRIDE  80     // 40 bf16 per row (32 data + pad) -> conflict-free LDSM
#define BN_STRIDE 272    // 136 bf16 per row for [K,N] B tiles
#define BUF_SZ    10240  // one operand buffer (max of 128*80, 32*272)
#define STAGE_SZ  (4*BUF_SZ)      // Ah, Al, Bh, Bl
#define SMEM_DYN  (2*STAGE_SZ)    // double buffered: 80 KB

// ---------------------------------------------------------------------------
// Scratch (static device globals — no runtime allocation)
// ---------------------------------------------------------------------------
__device__ __nv_bfloat16 g_xh[(size_t)NROWS*D_];
__device__ __nv_bfloat16 g_xl[(size_t)NROWS*D_];
__device__ __nv_bfloat16 g_wh[(size_t)4*D_*D_];
__device__ __nv_bfloat16 g_wl[(size_t)4*D_*D_];
__device__ __nv_bfloat16 g_qh[(size_t)NROWS*D_];
__device__ __nv_bfloat16 g_ql[(size_t)NROWS*D_];
__device__ __nv_bfloat16 g_kh[(size_t)NROWS*D_];
__device__ __nv_bfloat16 g_kl[(size_t)NROWS*D_];
__device__ __nv_bfloat16 g_vh[(size_t)NROWS*D_];
__device__ __nv_bfloat16 g_vl[(size_t)NROWS*D_];
__device__ __nv_bfloat16 g_yh[(size_t)NROWS*D_];
__device__ __nv_bfloat16 g_yl[(size_t)NROWS*D_];
__device__ float         g_s [(size_t)B_*S_*S_];    // fp32 scores
__device__ __nv_bfloat16 g_ah[(size_t)B_*S_*S_];    // attn hi
__device__ __nv_bfloat16 g_al[(size_t)B_*S_*S_];    // attn lo

// ---------------------------------------------------------------------------
// PTX helpers (all portable: sm_80-era, legal on base compute_103 target)
// ---------------------------------------------------------------------------
static __device__ __forceinline__ void cpa(u32 dst, const void* src) {
    asm volatile("cp.async.cg.shared.global [%0], [%1], 16;"
                 :: "r"(dst), "l"(src));
}
static __device__ __forceinline__ void ldsm4(u32 &r0,u32 &r1,u32 &r2,u32 &r3, u32 a) {
    asm volatile("ldmatrix.sync.aligned.m8n8.x4.shared.b16 {%0,%1,%2,%3}, [%4];"
                 : "=r"(r0),"=r"(r1),"=r"(r2),"=r"(r3) : "r"(a));
}
static __device__ __forceinline__ void ldsm4t(u32 &r0,u32 &r1,u32 &r2,u32 &r3, u32 a) {
    asm volatile("ldmatrix.sync.aligned.m8n8.x4.trans.shared.b16 {%0,%1,%2,%3}, [%4];"
                 : "=r"(r0),"=r"(r1),"=r"(r2),"=r"(r3) : "r"(a));
}
static __device__ __forceinline__ void mma16816(float* d, const u32* a, const u32* b) {
    asm volatile(
        "mma.sync.aligned.m16n8k16.row.col.f32.bf16.bf16.f32 "
        "{%0,%1,%2,%3}, {%4,%5,%6,%7}, {%8,%9}, {%0,%1,%2,%3};"
        : "+f"(d[0]),"+f"(d[1]),"+f"(d[2]),"+f"(d[3])
        : "r"(a[0]),"r"(a[1]),"r"(a[2]),"r"(a[3]), "r"(b[0]),"r"(b[1]));
}

static __device__ __forceinline__ void split_bf(float x, __nv_bfloat16& h, __nv_bfloat16& l) {
    h = __float2bfloat16(x);
    l = __float2bfloat16(x - __bfloat162float(h));
}
static __device__ __forceinline__ u32 pk(__nv_bfloat16 a, __nv_bfloat16 b) {
    return (u32)__bfloat16_as_ushort(a) | ((u32)__bfloat16_as_ushort(b) << 16);
}

// ---------------------------------------------------------------------------
// bf16x3 HMMA GEMM:  C[m,n] = alpha * sum_k A[m,k]*B(n,k)  (+bias[n])
//   A: [M,K] K-major hi/lo.
//   BNK=true : B is [N,K] K-major (NT gemm)   — QKV, scores, out
//   BNK=false: B is [K,N] N-major (NN gemm)   — attn @ V (ldmatrix.trans)
//   EPI 0: fp32 out (alpha, optional bias);  EPI 1: split bf16 hi/lo out.
// grid = (N/TN, M/TM, batch), 256 threads.
// ---------------------------------------------------------------------------
template <bool BNK, int EPI>
__global__ void __launch_bounds__(256, 2) gemm_k(
    const __nv_bfloat16* __restrict__ Ah, const __nv_bfloat16* __restrict__ Al,
    int lda, size_t abatch,
    const __nv_bfloat16* __restrict__ Bh, const __nv_bfloat16* __restrict__ Bl,
    int ldb, size_t bbatch,
    int K, float alpha, const float* __restrict__ bias,
    float* __restrict__ Cf, __nv_bfloat16* __restrict__ Ch, __nv_bfloat16* __restrict__ Cl,
    int ldc, size_t cbatch)
{
    extern __shared__ __align__(1024) char dsm[];
    const u32 sb   = (u32)__cvta_generic_to_shared(dsm);
    const int tid  = threadIdx.x;
    const int wid  = tid >> 5;
    const int lane = tid & 31;
    const int bm = blockIdx.y, bn = blockIdx.x, bz = blockIdx.z;
    const int warp_m = wid & 1;        // 2 warps along M
    const int warp_n = wid >> 1;       // 4 warps along N

    const __nv_bfloat16* pAh = Ah + (size_t)bz*abatch + (size_t)(bm*TM)*lda;
    const __nv_bfloat16* pAl = Al + (size_t)bz*abatch + (size_t)(bm*TM)*lda;
    const __nv_bfloat16* pBh;
    const __nv_bfloat16* pBl;
    if (BNK) {
        pBh = Bh + (size_t)bz*bbatch + (size_t)(bn*TN)*ldb;
        pBl = Bl + (size_t)bz*bbatch + (size_t)(bn*TN)*ldb;
    } else {
        pBh = Bh + (size_t)bz*bbatch + bn*TN;
        pBl = Bl + (size_t)bz*bbatch + bn*TN;
    }

    // ---- stage loader: 8 cp.async (16B) per thread ----
    auto load_stage = [&](int stg, int t) {
        const int k0 = t * TK;
        const u32 da = sb + stg * STAGE_SZ;
#pragma unroll
        for (int i = 0; i < 2; ++i) {
            const int idx = tid + i * 256;
            const int r = idx >> 2, c = idx & 3;            // 128 rows x 4 chunks
            const u32 d = da + r * A_STRIDE + c * 16;
            cpa(d,          pAh + (size_t)r * lda + k0 + c * 8);
            cpa(d + BUF_SZ, pAl + (size_t)r * lda + k0 + c * 8);
            if (BNK) {
                const u32 db = da + 2 * BUF_SZ + r * A_STRIDE + c * 16;
                cpa(db,          pBh + (size_t)r * ldb + k0 + c * 8);
                cpa(db + BUF_SZ, pBl + (size_t)r * ldb + k0 + c * 8);
            } else {
                const int rb = idx >> 4, cb = idx & 15;      // 32 rows x 16 chunks
                const u32 db = da + 2 * BUF_SZ + rb * BN_STRIDE + cb * 16;
                cpa(db,          pBh + (size_t)(k0 + rb) * ldb + cb * 8);
                cpa(db + BUF_SZ, pBl + (size_t)(k0 + rb) * ldb + cb * 8);
            }
        }
        asm volatile("cp.async.commit_group;");
    };

    // ---- ldmatrix lane offsets (bytes) ----
    const u32 aoff = ((warp_m * 64 + (lane & 15)) * 40 + (lane >> 4) * 8) * 2;
    u32 boff;
    if (BNK)
        boff = ((warp_n * 32 + ((lane >> 4) & 1) * 8 + (lane & 7)) * 40
                + ((lane >> 3) & 1) * 8) * 2;
    else
        boff = ((((lane >> 3) & 1) * 8 + (lane & 7)) * 136
                + warp_n * 32 + ((lane >> 4) & 1) * 8) * 2;

    float acc[4][4][4];
#pragma unroll
    for (int mt = 0; mt < 4; ++mt)
#pragma unroll
        for (int nt = 0; nt < 4; ++nt)
#pragma unroll
            for (int i = 0; i < 4; ++i) acc[mt][nt][i] = 0.f;

    // ---- mainloop compute on one stage (2 k16 steps, hh -> hl -> lh) ----
    auto compute = [&](int stg) {
        const u32 sa = sb + stg * STAGE_SZ;
        const u32 ab = sa + aoff;
        const u32 bb = sa + 2 * BUF_SZ + boff;
#pragma unroll
        for (int kk = 0; kk < 2; ++kk) {
            u32 ahf[4][4], bhf[4][2], blf[4][2], alf[4][4];
#pragma unroll
            for (int mt = 0; mt < 4; ++mt)
                ldsm4(ahf[mt][0], ahf[mt][1], ahf[mt][2], ahf[mt][3],
                      ab + mt * (16 * A_STRIDE) + kk * 32);
#pragma unroll
            for (int n2 = 0; n2 < 2; ++n2) {
                u32 r0, r1, r2, r3;
                if (BNK) ldsm4 (r0, r1, r2, r3, bb + n2 * (16 * A_STRIDE) + kk * 32);
                else     ldsm4t(r0, r1, r2, r3, bb + n2 * 32 + kk * (16 * BN_STRIDE));
                bhf[n2*2][0] = r0; bhf[n2*2][1] = r1;
                bhf[n2*2+1][0] = r2; bhf[n2*2+1][1] = r3;
            }
#pragma unroll
            for (int mt = 0; mt < 4; ++mt)
#pragma unroll
                for (int nt = 0; nt < 4; ++nt)
                    mma16816(acc[mt][nt], ahf[mt], bhf[nt]);      // hi*hi

#pragma unroll
            for (int n2 = 0; n2 < 2; ++n2) {
                u32 r0, r1, r2, r3;
                if (BNK) ldsm4 (r0, r1, r2, r3, bb + BUF_SZ + n2 * (16 * A_STRIDE) + kk * 32);
                else     ldsm4t(r0, r1, r2, r3, bb + BUF_SZ + n2 * 32 + kk * (16 * BN_STRIDE));
                blf[n2*2][0] = r0; blf[n2*2][1] = r1;
                blf[n2*2+1][0] = r2; blf[n2*2+1][1] = r3;
            }
#pragma unroll
            for (int mt = 0; mt < 4; ++mt)
#pragma unroll
                for (int nt = 0; nt < 4; ++nt)
                    mma16816(acc[mt][nt], ahf[mt], blf[nt]);      // hi*lo

#pragma unroll
            for (int mt = 0; mt < 4; ++mt)
                ldsm4(alf[mt][0], alf[mt][1], alf[mt][2], alf[mt][3],
                      ab + BUF_SZ + mt * (16 * A_STRIDE) + kk * 32);
#pragma unroll
            for (int mt = 0; mt < 4; ++mt)
#pragma unroll
                for (int nt = 0; nt < 4; ++nt)
                    mma16816(acc[mt][nt], alf[mt], bhf[nt]);      // lo*hi
        }
    };

    const int T = K / TK;
    load_stage(0, 0);
    for (int t = 0; t < T; ++t) {
        if (t + 1 < T) {
            load_stage((t + 1) & 1, t + 1);
            asm volatile("cp.async.wait_group 1;");
        } else {
            asm volatile("cp.async.wait_group 0;");
        }
        __syncthreads();
        compute(t & 1);
        __syncthreads();
    }

    // ---- epilogue ----
    const int g  = lane >> 2;
    const int tc = lane & 3;
    const int row_w = bm * TM + warp_m * 64;
    const int col_w = bn * TN + warp_n * 32;
#pragma unroll
    for (int mt = 0; mt < 4; ++mt) {
#pragma unroll
        for (int nt = 0; nt < 4; ++nt) {
            const int r0 = row_w + mt * 16 + g;
            const int c0 = col_w + nt * 8 + tc * 2;
            float v0 = acc[mt][nt][0], v1 = acc[mt][nt][1];
            float v2 = acc[mt][nt][2], v3 = acc[mt][nt][3];
            if constexpr (EPI == 0) {
                v0 *= alpha; v1 *= alpha; v2 *= alpha; v3 *= alpha;
                if (bias) {
                    const float b0 = bias[c0], b1 = bias[c0 + 1];
                    v0 += b0; v1 += b1; v2 += b0; v3 += b1;
                }
                float* base = Cf + (size_t)bz * cbatch;
                *reinterpret_cast<float2*>(base + (size_t)r0 * ldc + c0)       = make_float2(v0, v1);
                *reinterpret_cast<float2*>(base + (size_t)(r0 + 8) * ldc + c0) = make_float2(v2, v3);
            } else {
                if (bias) {
                    const float b0 = bias[c0], b1 = bias[c0 + 1];
                    v0 += b0; v1 += b1; v2 += b0; v3 += b1;
                }
                __nv_bfloat16 h0,l0,h1,l1,h2,l2,h3,l3;
                split_bf(v0,h0,l0); split_bf(v1,h1,l1);
                split_bf(v2,h2,l2); split_bf(v3,h3,l3);
                __nv_bfloat16* dh = Ch + (size_t)bz * cbatch;
                __nv_bfloat16* dl = Cl + (size_t)bz * cbatch;
                *reinterpret_cast<u32*>(dh + (size_t)r0 * ldc + c0)       = pk(h0, h1);
                *reinterpret_cast<u32*>(dl + (size_t)r0 * ldc + c0)       = pk(l0, l1);
                *reinterpret_cast<u32*>(dh + (size_t)(r0 + 8) * ldc + c0) = pk(h2, h3);
                *reinterpret_cast<u32*>(dl + (size_t)(r0 + 8) * ldc + c0) = pk(l2, l3);
            }
        }
    }
}

// ---------------------------------------------------------------------------
// Prologue: xp = x + pos -> bf16 hi/lo ; weights -> bf16 hi/lo
// ---------------------------------------------------------------------------
__global__ void __launch_bounds__(256) k_prep_x(
    const float4* __restrict__ x, const float4* __restrict__ pos,
    __nv_bfloat16* __restrict__ xh, __nv_bfloat16* __restrict__ xl)
{
    const size_t i = (size_t)blockIdx.x * 256 + threadIdx.x;  // < 2097152
    float4 a = x[i];
    const float4 p = pos[i & 262143u];                        // (S_*D_/4)-1
    a.x += p.x; a.y += p.y; a.z += p.z; a.w += p.w;
    __nv_bfloat16 h0,l0,h1,l1,h2,l2,h3,l3;
    split_bf(a.x,h0,l0); split_bf(a.y,h1,l1); split_bf(a.z,h2,l2); split_bf(a.w,h3,l3);
    *reinterpret_cast<uint2*>(xh + i*4) = make_uint2(pk(h0,h1), pk(h2,h3));
    *reinterpret_cast<uint2*>(xl + i*4) = make_uint2(pk(l0,l1), pk(l2,l3));
}

__global__ void __launch_bounds__(256) k_prep_w(
    const float4* __restrict__ Wq, const float4* __restrict__ Wk,
    const float4* __restrict__ Wv, const float4* __restrict__ Wd,
    __nv_bfloat16* __restrict__ wh, __nv_bfloat16* __restrict__ wl)
{
    const int w = blockIdx.y;
    const float4* src = (w == 0) ? Wq : (w == 1) ? Wk : (w == 2) ? Wv : Wd;
    const size_t i = (size_t)blockIdx.x * 256 + threadIdx.x;  // < 65536
    const float4 a = src[i];
    __nv_bfloat16 h0,l0,h1,l1,h2,l2,h3,l3;
    split_bf(a.x,h0,l0); split_bf(a.y,h1,l1); split_bf(a.z,h2,l2); split_bf(a.w,h3,l3);
    const size_t o = (size_t)w * 262144 + i * 4;
    *reinterpret_cast<uint2*>(wh + o) = make_uint2(pk(h0,h1), pk(h2,h3));
    *reinterpret_cast<uint2*>(wl + o) = make_uint2(pk(l0,l1), pk(l2,l3));
}

// ---------------------------------------------------------------------------
// Row softmax over 2048; outputs attn split into bf16 hi/lo
// ---------------------------------------------------------------------------
__global__ void __launch_bounds__(256) k_softmax(
    const float* __restrict__ s,
    __nv_bfloat16* __restrict__ ah, __nv_bfloat16* __restrict__ al)
{
    const size_t base = (size_t)blockIdx.x * S_;
    const float* p = s + base;
    const int tid = threadIdx.x;
    __shared__ float red[8];

    float v[8];
    float mx = -3.4e38f;
#pragma unroll
    for (int i = 0; i < 8; ++i) { v[i] = p[tid + 256 * i]; mx = fmaxf(mx, v[i]); }
#pragma unroll
    for (int o = 16; o > 0; o >>= 1)
        mx = fmaxf(mx, __shfl_xor_sync(0xffffffffu, mx, o));
    if ((tid & 31) == 0) red[tid >> 5] = mx;
    __syncthreads();
    mx = red[0];
#pragma unroll
    for (int w = 1; w < 8; ++w) mx = fmaxf(mx, red[w]);

    float sum = 0.f;
#pragma unroll
    for (int i = 0; i < 8; ++i) { v[i] = expf(v[i] - mx); sum += v[i]; }
#pragma unroll
    for (int o = 16; o > 0; o >>= 1)
        sum += __shfl_xor_sync(0xffffffffu, sum, o);
    __syncthreads();
    if ((tid & 31) == 0) red[tid >> 5] = sum;
    __syncthreads();
    float tot = 0.f;
#pragma unroll
    for (int w = 0; w < 8; ++w) tot += red[w];
    const float inv = 1.0f / tot;

#pragma unroll
    for (int i = 0; i < 8; ++i) {
        const float q = v[i] * inv;
        __nv_bfloat16 h, l;
        split_bf(q, h, l);
        ah[base + tid + 256 * i] = h;
        al[base + tid + 256 * i] = l;
    }
}

// ---------------------------------------------------------------------------
// Launch
// ---------------------------------------------------------------------------
extern "C" void kernel_launch(void* const* d_in, const int* in_sizes, int n_in,
                              void* d_out, int out_size)
{
    const float* x   = (const float*)d_in[0];
    const float* pos = (const float*)d_in[1];
    const float* Wq  = (const float*)d_in[2];
    const float* bq  = (const float*)d_in[3];
    const float* Wk  = (const float*)d_in[4];
    const float* bk  = (const float*)d_in[5];
    const float* Wv  = (const float*)d_in[6];
    const float* bv  = (const float*)d_in[7];
    const float* Wd  = (const float*)d_in[8];
    const float* bd  = (const float*)d_in[9];
    float* out = (float*)d_out;

    __nv_bfloat16 *xh,*xl,*wh,*wl,*qh,*ql,*kh,*kl,*vh,*vl,*yh,*yl,*ah,*al;
    float* sc;
    cudaGetSymbolAddress((void**)&xh, g_xh); cudaGetSymbolAddress((void**)&xl, g_xl);
    cudaGetSymbolAddress((void**)&wh, g_wh); cudaGetSymbolAddress((void**)&wl, g_wl);
    cudaGetSymbolAddress((void**)&qh, g_qh); cudaGetSymbolAddress((void**)&ql, g_ql);
    cudaGetSymbolAddress((void**)&kh, g_kh); cudaGetSymbolAddress((void**)&kl, g_kl);
    cudaGetSymbolAddress((void**)&vh, g_vh); cudaGetSymbolAddress((void**)&vl, g_vl);
    cudaGetSymbolAddress((void**)&yh, g_yh); cudaGetSymbolAddress((void**)&yl, g_yl);
    cudaGetSymbolAddress((void**)&ah, g_ah); cudaGetSymbolAddress((void**)&al, g_al);
    cudaGetSymbolAddress((void**)&sc, g_s);

    cudaFuncSetAttribute(gemm_k<true,0>,  cudaFuncAttributeMaxDynamicSharedMemorySize, SMEM_DYN);
    cudaFuncSetAttribute(gemm_k<true,1>,  cudaFuncAttributeMaxDynamicSharedMemorySize, SMEM_DYN);
    cudaFuncSetAttribute(gemm_k<false,1>, cudaFuncAttributeMaxDynamicSharedMemorySize, SMEM_DYN);

    const size_t SD = (size_t)S_ * D_;   // 1048576
    const size_t SS = (size_t)S_ * S_;   // 4194304
    const size_t WW = (size_t)D_ * D_;   // 262144
    const float scale = 0.044194173824159216f;  // 1/sqrt(512)

    k_prep_x<<<8192, 256>>>((const float4*)x, (const float4*)pos, xh, xl);
    k_prep_w<<<dim3(256, 4), 256>>>((const float4*)Wq, (const float4*)Wk,
                                    (const float4*)Wv, (const float4*)Wd, wh, wl);

    // q/k/v = xp @ W^T + b   (split hi/lo outputs)
    gemm_k<true,1><<<dim3(4, 128, 1), 256, SMEM_DYN>>>(
        xh, xl, D_, 0, wh,        wl,        D_, 0, D_, 1.f, bq,
        nullptr, qh, ql, D_, 0);
    gemm_k<true,1><<<dim3(4, 128, 1), 256, SMEM_DYN>>>(
        xh, xl, D_, 0, wh + WW,   wl + WW,   D_, 0, D_, 1.f, bk,
        nullptr, kh, kl, D_, 0);
    gemm_k<true,1><<<dim3(4, 128, 1), 256, SMEM_DYN>>>(
        xh, xl, D_, 0, wh + 2*WW, wl + 2*WW, D_, 0, D_, 1.f, bv,
        nullptr, vh, vl, D_, 0);

    // scores = scale * q @ k^T   (fp32)
    gemm_k<true,0><<<dim3(16, 16, 8), 256, SMEM_DYN>>>(
        qh, ql, D_, SD, kh, kl, D_, SD, D_, scale, nullptr,
        sc, nullptr, nullptr, S_, SS);

    // softmax -> attn hi/lo
    k_softmax<<<B_ * S_, 256>>>(sc, ah, al);

    // y = attn @ v   (NN gemm via ldmatrix.trans on V)
    gemm_k<false,1><<<dim3(4, 16, 8), 256, SMEM_DYN>>>(
        ah, al, S_, SS, vh, vl, D_, SD, S_, 1.f, nullptr,
        nullptr, yh, yl, D_, SD);

    // out = y @ Wd^T + bd   (fp32)
    gemm_k<true,0><<<dim3(4, 128, 1), 256, SMEM_DYN>>>(
        yh, yl, D_, 0, wh + 3*WW, wl + 3*WW, D_, 0, D_, 1.f, bd,
        out, nullptr, nullptr, D_, 0);
}

// round 6
// speedup vs baseline: 2.4122x; 1.0080x over previous
#include <cuda_runtime.h>
#include <cuda_bf16.h>
#include <stdint.h>

typedef unsigned int u32;

#define B_    8
#define S_    2048
#define D_    512
#define NROWS 16384
#define QKVW  1536              // fused q|k|v row width

// Tiling
#define TM 64
#define TN 128
#define TK 32

// SMEM layout (bytes)
#define A_STRIDE  80     // 40 bf16 per row (32 data + pad) -> conflict-free LDSM
#define BN_STRIDE 272    // 136 bf16 per row for [K,N] B tiles (32 rows = 8704B)
#define A_BUF     5120   // 64 rows * 80B
#define B_BUF     10240  // 128 rows * 80B (or 32*272 = 8704 for NN)
#define AOFF_LO   5120
#define BOFF_HI   10240
#define BOFF_LO   20480
#define STAGE_SZ  30720          // Ah, Al, Bh, Bl
#define SMEM_DYN  (2*STAGE_SZ)   // double buffered: 60 KB -> 3 CTAs/SM

// ---------------------------------------------------------------------------
// Scratch (static device globals — no runtime allocation)
// ---------------------------------------------------------------------------
__device__ __nv_bfloat16 g_xh[(size_t)NROWS*D_];
__device__ __nv_bfloat16 g_xl[(size_t)NROWS*D_];
__device__ __nv_bfloat16 g_wh[(size_t)4*D_*D_];   // Wq|Wk|Wv|Wd rows
__device__ __nv_bfloat16 g_wl[(size_t)4*D_*D_];
__device__ float         g_bias[QKVW];            // bq|bk|bv packed
__device__ __nv_bfloat16 g_qkvh[(size_t)NROWS*QKVW];
__device__ __nv_bfloat16 g_qkvl[(size_t)NROWS*QKVW];
__device__ __nv_bfloat16 g_yh[(size_t)NROWS*D_];
__device__ __nv_bfloat16 g_yl[(size_t)NROWS*D_];
__device__ float         g_s [(size_t)B_*S_*S_];  // fp32 scores
__device__ __nv_bfloat16 g_ah[(size_t)B_*S_*S_];  // attn hi
__device__ __nv_bfloat16 g_al[(size_t)B_*S_*S_];  // attn lo

// ---------------------------------------------------------------------------
// PTX helpers (portable sm_80-era; legal on base compute_103 target)
// ---------------------------------------------------------------------------
static __device__ __forceinline__ void cpa(u32 dst, const void* src) {
    asm volatile("cp.async.cg.shared.global [%0], [%1], 16;"
                 :: "r"(dst), "l"(src));
}
static __device__ __forceinline__ void ldsm4(u32 &r0,u32 &r1,u32 &r2,u32 &r3, u32 a) {
    asm volatile("ldmatrix.sync.aligned.m8n8.x4.shared.b16 {%0,%1,%2,%3}, [%4];"
                 : "=r"(r0),"=r"(r1),"=r"(r2),"=r"(r3) : "r"(a));
}
static __device__ __forceinline__ void ldsm4t(u32 &r0,u32 &r1,u32 &r2,u32 &r3, u32 a) {
    asm volatile("ldmatrix.sync.aligned.m8n8.x4.trans.shared.b16 {%0,%1,%2,%3}, [%4];"
                 : "=r"(r0),"=r"(r1),"=r"(r2),"=r"(r3) : "r"(a));
}
static __device__ __forceinline__ void mma16816(float* d, const u32* a, const u32* b) {
    asm volatile(
        "mma.sync.aligned.m16n8k16.row.col.f32.bf16.bf16.f32 "
        "{%0,%1,%2,%3}, {%4,%5,%6,%7}, {%8,%9}, {%0,%1,%2,%3};"
        : "+f"(d[0]),"+f"(d[1]),"+f"(d[2]),"+f"(d[3])
        : "r"(a[0]),"r"(a[1]),"r"(a[2]),"r"(a[3]), "r"(b[0]),"r"(b[1]));
}

static __device__ __forceinline__ void split_bf(float x, __nv_bfloat16& h, __nv_bfloat16& l) {
    h = __float2bfloat16(x);
    l = __float2bfloat16(x - __bfloat162float(h));
}
static __device__ __forceinline__ u32 pk(__nv_bfloat16 a, __nv_bfloat16 b) {
    return (u32)__bfloat16_as_ushort(a) | ((u32)__bfloat16_as_ushort(b) << 16);
}

// ---------------------------------------------------------------------------
// bf16x3 HMMA GEMM:  C[m,n] = alpha * sum_k A[m,k]*B(n,k)  (+bias[n])
//   A: [M,K] K-major hi/lo.
//   BNK=true : B is [N,K] K-major (NT gemm) ; BNK=false: B is [K,N] (NN gemm)
//   EPI 0: fp32 out (alpha, optional bias);  EPI 1: split bf16 hi/lo out.
// grid = (N/TN, M/TM, batch), 256 threads, 3 CTAs/SM.
// ---------------------------------------------------------------------------
template <bool BNK, int EPI>
__global__ void __launch_bounds__(256, 3) gemm_k(
    const __nv_bfloat16* __restrict__ Ah, const __nv_bfloat16* __restrict__ Al,
    int lda, size_t abatch,
    const __nv_bfloat16* __restrict__ Bh, const __nv_bfloat16* __restrict__ Bl,
    int ldb, size_t bbatch,
    int K, float alpha, const float* __restrict__ bias,
    float* __restrict__ Cf, __nv_bfloat16* __restrict__ Ch, __nv_bfloat16* __restrict__ Cl,
    int ldc, size_t cbatch)
{
    extern __shared__ __align__(1024) char dsm[];
    const u32 sb   = (u32)__cvta_generic_to_shared(dsm);
    const int tid  = threadIdx.x;
    const int wid  = tid >> 5;
    const int lane = tid & 31;
    const int bm = blockIdx.y, bn = blockIdx.x, bz = blockIdx.z;
    const int warp_m = wid & 1;        // 2 warps along M (32 rows each)
    const int warp_n = wid >> 1;       // 4 warps along N (32 cols each)

    const __nv_bfloat16* pAh = Ah + (size_t)bz*abatch + (size_t)(bm*TM)*lda;
    const __nv_bfloat16* pAl = Al + (size_t)bz*abatch + (size_t)(bm*TM)*lda;
    const __nv_bfloat16* pBh;
    const __nv_bfloat16* pBl;
    if (BNK) {
        pBh = Bh + (size_t)bz*bbatch + (size_t)(bn*TN)*ldb;
        pBl = Bl + (size_t)bz*bbatch + (size_t)(bn*TN)*ldb;
    } else {
        pBh = Bh + (size_t)bz*bbatch + bn*TN;
        pBl = Bl + (size_t)bz*bbatch + bn*TN;
    }

    // ---- stage loader: 6 cp.async (16B) per thread ----
    auto load_stage = [&](int stg, int t) {
        const int k0 = t * TK;
        const u32 da = sb + stg * STAGE_SZ;
        {   // A: 64 rows x 4 chunks
            const int r = tid >> 2, c = tid & 3;
            const u32 d = da + r * A_STRIDE + c * 16;
            cpa(d,           pAh + (size_t)r * lda + k0 + c * 8);
            cpa(d + AOFF_LO, pAl + (size_t)r * lda + k0 + c * 8);
        }
#pragma unroll
        for (int i = 0; i < 2; ++i) {
            const int idx = tid + i * 256;
            if (BNK) {
                const int r = idx >> 2, c = idx & 3;        // 128 rows x 4 chunks
                const u32 db = da + BOFF_HI + r * A_STRIDE + c * 16;
                cpa(db,         pBh + (size_t)r * ldb + k0 + c * 8);
                cpa(db + B_BUF, pBl + (size_t)r * ldb + k0 + c * 8);
            } else {
                const int rb = idx >> 4, cb = idx & 15;     // 32 rows x 16 chunks
                const u32 db = da + BOFF_HI + rb * BN_STRIDE + cb * 16;
                cpa(db,         pBh + (size_t)(k0 + rb) * ldb + cb * 8);
                cpa(db + B_BUF, pBl + (size_t)(k0 + rb) * ldb + cb * 8);
            }
        }
        asm volatile("cp.async.commit_group;");
    };

    // ---- ldmatrix lane offsets (bytes) ----
    const u32 aoff = ((warp_m * 32 + (lane & 15)) * 40 + (lane >> 4) * 8) * 2;
    u32 boff;
    if (BNK)
        boff = ((warp_n * 32 + ((lane >> 4) & 1) * 8 + (lane & 7)) * 40
                + ((lane >> 3) & 1) * 8) * 2;
    else
        boff = ((((lane >> 3) & 1) * 8 + (lane & 7)) * 136
                + warp_n * 32 + ((lane >> 4) & 1) * 8) * 2;

    float acc[2][4][4];
#pragma unroll
    for (int mt = 0; mt < 2; ++mt)
#pragma unroll
        for (int nt = 0; nt < 4; ++nt)
#pragma unroll
            for (int i = 0; i < 4; ++i) acc[mt][nt][i] = 0.f;

    // ---- mainloop compute on one stage (2 k16 steps, hh -> hl -> lh) ----
    auto compute = [&](int stg) {
        const u32 sa = sb + stg * STAGE_SZ;
        const u32 ab = sa + aoff;
        const u32 bb = sa + BOFF_HI + boff;
#pragma unroll
        for (int kk = 0; kk < 2; ++kk) {
            u32 ahf[2][4], bhf[4][2], blf[4][2], alf[2][4];
#pragma unroll
            for (int mt = 0; mt < 2; ++mt)
                ldsm4(ahf[mt][0], ahf[mt][1], ahf[mt][2], ahf[mt][3],
                      ab + mt * (16 * A_STRIDE) + kk * 32);
#pragma unroll
            for (int n2 = 0; n2 < 2; ++n2) {
                u32 r0, r1, r2, r3;
                if (BNK) ldsm4 (r0, r1, r2, r3, bb + n2 * (16 * A_STRIDE) + kk * 32);
                else     ldsm4t(r0, r1, r2, r3, bb + n2 * 32 + kk * (16 * BN_STRIDE));
                bhf[n2*2][0] = r0; bhf[n2*2][1] = r1;
                bhf[n2*2+1][0] = r2; bhf[n2*2+1][1] = r3;
            }
#pragma unroll
            for (int mt = 0; mt < 2; ++mt)
#pragma unroll
                for (int nt = 0; nt < 4; ++nt)
                    mma16816(acc[mt][nt], ahf[mt], bhf[nt]);      // hi*hi

#pragma unroll
            for (int n2 = 0; n2 < 2; ++n2) {
                u32 r0, r1, r2, r3;
                if (BNK) ldsm4 (r0, r1, r2, r3, bb + B_BUF + n2 * (16 * A_STRIDE) + kk * 32);
                else     ldsm4t(r0, r1, r2, r3, bb + B_BUF + n2 * 32 + kk * (16 * BN_STRIDE));
                blf[n2*2][0] = r0; blf[n2*2][1] = r1;
                blf[n2*2+1][0] = r2; blf[n2*2+1][1] = r3;
            }
#pragma unroll
            for (int mt = 0; mt < 2; ++mt)
#pragma unroll
                for (int nt = 0; nt < 4; ++nt)
                    mma16816(acc[mt][nt], ahf[mt], blf[nt]);      // hi*lo

#pragma unroll
            for (int mt = 0; mt < 2; ++mt)
                ldsm4(alf[mt][0], alf[mt][1], alf[mt][2], alf[mt][3],
                      ab + AOFF_LO + mt * (16 * A_STRIDE) + kk * 32);
#pragma unroll
            for (int mt = 0; mt < 2; ++mt)
#pragma unroll
                for (int nt = 0; nt < 4; ++nt)
                    mma16816(acc[mt][nt], alf[mt], bhf[nt]);      // lo*hi
        }
    };

    const int T = K / TK;
    load_stage(0, 0);
    for (int t = 0; t < T; ++t) {
        if (t + 1 < T) {
            load_stage((t + 1) & 1, t + 1);
            asm volatile("cp.async.wait_group 1;");
        } else {
            asm volatile("cp.async.wait_group 0;");
        }
        __syncthreads();
        compute(t & 1);
        __syncthreads();
    }

    // ---- epilogue ----
    const int g  = lane >> 2;
    const int tc = lane & 3;
    const int row_w = bm * TM + warp_m * 32;
    const int col_w = bn * TN + warp_n * 32;
#pragma unroll
    for (int mt = 0; mt < 2; ++mt) {
#pragma unroll
        for (int nt = 0; nt < 4; ++nt) {
            const int r0 = row_w + mt * 16 + g;
            const int c0 = col_w + nt * 8 + tc * 2;
            float v0 = acc[mt][nt][0], v1 = acc[mt][nt][1];
            float v2 = acc[mt][nt][2], v3 = acc[mt][nt][3];
            if constexpr (EPI == 0) {
                v0 *= alpha; v1 *= alpha; v2 *= alpha; v3 *= alpha;
                if (bias) {
                    const float b0 = bias[c0], b1 = bias[c0 + 1];
                    v0 += b0; v1 += b1; v2 += b0; v3 += b1;
                }
                float* base = Cf + (size_t)bz * cbatch;
                *reinterpret_cast<float2*>(base + (size_t)r0 * ldc + c0)       = make_float2(v0, v1);
                *reinterpret_cast<float2*>(base + (size_t)(r0 + 8) * ldc + c0) = make_float2(v2, v3);
            } else {
                if (bias) {
                    const float b0 = bias[c0], b1 = bias[c0 + 1];
                    v0 += b0; v1 += b1; v2 += b0; v3 += b1;
                }
                __nv_bfloat16 h0,l0,h1,l1,h2,l2,h3,l3;
                split_bf(v0,h0,l0); split_bf(v1,h1,l1);
                split_bf(v2,h2,l2); split_bf(v3,h3,l3);
                __nv_bfloat16* dh = Ch + (size_t)bz * cbatch;
                __nv_bfloat16* dl = Cl + (size_t)bz * cbatch;
                *reinterpret_cast<u32*>(dh + (size_t)r0 * ldc + c0)       = pk(h0, h1);
                *reinterpret_cast<u32*>(dl + (size_t)r0 * ldc + c0)       = pk(l0, l1);
                *reinterpret_cast<u32*>(dh + (size_t)(r0 + 8) * ldc + c0) = pk(h2, h3);
                *reinterpret_cast<u32*>(dl + (size_t)(r0 + 8) * ldc + c0) = pk(l2, l3);
            }
        }
    }
}

// ---------------------------------------------------------------------------
// Prologue: xp = x + pos -> bf16 hi/lo ; weights -> bf16 hi/lo ; packed bias
// ---------------------------------------------------------------------------
__global__ void __launch_bounds__(256) k_prep_x(
    const float4* __restrict__ x, const float4* __restrict__ pos,
    __nv_bfloat16* __restrict__ xh, __nv_bfloat16* __restrict__ xl)
{
    const size_t i = (size_t)blockIdx.x * 256 + threadIdx.x;  // < 2097152
    float4 a = x[i];
    const float4 p = pos[i & 262143u];                        // (S_*D_/4)-1
    a.x += p.x; a.y += p.y; a.z += p.z; a.w += p.w;
    __nv_bfloat16 h0,l0,h1,l1,h2,l2,h3,l3;
    split_bf(a.x,h0,l0); split_bf(a.y,h1,l1); split_bf(a.z,h2,l2); split_bf(a.w,h3,l3);
    *reinterpret_cast<uint2*>(xh + i*4) = make_uint2(pk(h0,h1), pk(h2,h3));
    *reinterpret_cast<uint2*>(xl + i*4) = make_uint2(pk(l0,l1), pk(l2,l3));
}

__global__ void __launch_bounds__(256) k_prep_w(
    const float4* __restrict__ Wq, const float4* __restrict__ Wk,
    const float4* __restrict__ Wv, const float4* __restrict__ Wd,
    const float* __restrict__ bq, const float* __restrict__ bk,
    const float* __restrict__ bv,
    __nv_bfloat16* __restrict__ wh, __nv_bfloat16* __restrict__ wl,
    float* __restrict__ bias)
{
    const int w = blockIdx.y;
    const float4* src = (w == 0) ? Wq : (w == 1) ? Wk : (w == 2) ? Wv : Wd;
    const size_t i = (size_t)blockIdx.x * 256 + threadIdx.x;  // < 65536
    const float4 a = src[i];
    __nv_bfloat16 h0,l0,h1,l1,h2,l2,h3,l3;
    split_bf(a.x,h0,l0); split_bf(a.y,h1,l1); split_bf(a.z,h2,l2); split_bf(a.w,h3,l3);
    const size_t o = (size_t)w * 262144 + i * 4;
    *reinterpret_cast<uint2*>(wh + o) = make_uint2(pk(h0,h1), pk(h2,h3));
    *reinterpret_cast<uint2*>(wl + o) = make_uint2(pk(l0,l1), pk(l2,l3));
    // packed bias (first 512 threads of the first x-block per w<3)
    if (w < 3 && blockIdx.x < 2) {
        const int j = blockIdx.x * 256 + threadIdx.x;         // 0..511
        const float* bsrc = (w == 0) ? bq : (w == 1) ? bk : bv;
        bias[w * 512 + j] = bsrc[j];
    }
}

// ---------------------------------------------------------------------------
// Row softmax over 2048; outputs attn split into bf16 hi/lo
// ---------------------------------------------------------------------------
__global__ void __launch_bounds__(256) k_softmax(
    const float* __restrict__ s,
    __nv_bfloat16* __restrict__ ah, __nv_bfloat16* __restrict__ al)
{
    const size_t base = (size_t)blockIdx.x * S_;
    const float* p = s + base;
    const int tid = threadIdx.x;
    __shared__ float red[8];

    float v[8];
    float mx = -3.4e38f;
#pragma unroll
    for (int i = 0; i < 8; ++i) { v[i] = p[tid + 256 * i]; mx = fmaxf(mx, v[i]); }
#pragma unroll
    for (int o = 16; o > 0; o >>= 1)
        mx = fmaxf(mx, __shfl_xor_sync(0xffffffffu, mx, o));
    if ((tid & 31) == 0) red[tid >> 5] = mx;
    __syncthreads();
    mx = red[0];
#pragma unroll
    for (int w = 1; w < 8; ++w) mx = fmaxf(mx, red[w]);

    float sum = 0.f;
#pragma unroll
    for (int i = 0; i < 8; ++i) { v[i] = expf(v[i] - mx); sum += v[i]; }
#pragma unroll
    for (int o = 16; o > 0; o >>= 1)
        sum += __shfl_xor_sync(0xffffffffu, sum, o);
    __syncthreads();
    if ((tid & 31) == 0) red[tid >> 5] = sum;
    __syncthreads();
    float tot = 0.f;
#pragma unroll
    for (int w = 0; w < 8; ++w) tot += red[w];
    const float inv = 1.0f / tot;

#pragma unroll
    for (int i = 0; i < 8; ++i) {
        const float q = v[i] * inv;
        __nv_bfloat16 h, l;
        split_bf(q, h, l);
        ah[base + tid + 256 * i] = h;
        al[base + tid + 256 * i] = l;
    }
}

// ---------------------------------------------------------------------------
// Launch
// ---------------------------------------------------------------------------
extern "C" void kernel_launch(void* const* d_in, const int* in_sizes, int n_in,
                              void* d_out, int out_size)
{
    const float* x   = (const float*)d_in[0];
    const float* pos = (const float*)d_in[1];
    const float* Wq  = (const float*)d_in[2];
    const float* bq  = (const float*)d_in[3];
    const float* Wk  = (const float*)d_in[4];
    const float* bk  = (const float*)d_in[5];
    const float* Wv  = (const float*)d_in[6];
    const float* bv  = (const float*)d_in[7];
    const float* Wd  = (const float*)d_in[8];
    const float* bd  = (const float*)d_in[9];
    float* out = (float*)d_out;

    __nv_bfloat16 *xh,*xl,*wh,*wl,*qkvh,*qkvl,*yh,*yl,*ah,*al;
    float *sc, *bias;
    cudaGetSymbolAddress((void**)&xh,   g_xh);   cudaGetSymbolAddress((void**)&xl,   g_xl);
    cudaGetSymbolAddress((void**)&wh,   g_wh);   cudaGetSymbolAddress((void**)&wl,   g_wl);
    cudaGetSymbolAddress((void**)&qkvh, g_qkvh); cudaGetSymbolAddress((void**)&qkvl, g_qkvl);
    cudaGetSymbolAddress((void**)&yh,   g_yh);   cudaGetSymbolAddress((void**)&yl,   g_yl);
    cudaGetSymbolAddress((void**)&ah,   g_ah);   cudaGetSymbolAddress((void**)&al,   g_al);
    cudaGetSymbolAddress((void**)&sc,   g_s);    cudaGetSymbolAddress((void**)&bias, g_bias);

    cudaFuncSetAttribute(gemm_k<true,0>,  cudaFuncAttributeMaxDynamicSharedMemorySize, SMEM_DYN);
    cudaFuncSetAttribute(gemm_k<true,1>,  cudaFuncAttributeMaxDynamicSharedMemorySize, SMEM_DYN);
    cudaFuncSetAttribute(gemm_k<false,1>, cudaFuncAttributeMaxDynamicSharedMemorySize, SMEM_DYN);

    const size_t SQ = (size_t)S_ * QKVW;  // batch stride in qkv buffer
    const size_t SS = (size_t)S_ * S_;    // 4194304
    const size_t SD = (size_t)S_ * D_;    // 1048576
    const size_t WW = (size_t)D_ * D_;    // 262144
    const float scale = 0.044194173824159216f;  // 1/sqrt(512)

    k_prep_x<<<8192, 256>>>((const float4*)x, (const float4*)pos, xh, xl);
    k_prep_w<<<dim3(256, 4), 256>>>((const float4*)Wq, (const float4*)Wk,
                                    (const float4*)Wv, (const float4*)Wd,
                                    bq, bk, bv, wh, wl, bias);

    // qkv = xp @ [Wq|Wk|Wv]^T + [bq|bk|bv]   (fused, split hi/lo, ldc=1536)
    gemm_k<true,1><<<dim3(QKVW/TN, NROWS/TM, 1), 256, SMEM_DYN>>>(
        xh, xl, D_, 0, wh, wl, D_, 0, D_, 1.f, bias,
        nullptr, qkvh, qkvl, QKVW, 0);

    // scores = scale * q @ k^T   (fp32); q at col 0, k at col 512 of qkv
    gemm_k<true,0><<<dim3(S_/TN, S_/TM, B_), 256, SMEM_DYN>>>(
        qkvh, qkvl, QKVW, SQ, qkvh + 512, qkvl + 512, QKVW, SQ,
        D_, scale, nullptr, sc, nullptr, nullptr, S_, SS);

    // softmax -> attn hi/lo
    k_softmax<<<B_ * S_, 256>>>(sc, ah, al);

    // y = attn @ v   (NN gemm via ldmatrix.trans); v at col 1024 of qkv
    gemm_k<false,1><<<dim3(D_/TN, S_/TM, B_), 256, SMEM_DYN>>>(
        ah, al, S_, SS, qkvh + 1024, qkvl + 1024, QKVW, SQ,
        S_, 1.f, nullptr, nullptr, yh, yl, D_, SD);

    // out = y @ Wd^T + bd   (fp32)
    gemm_k<true,0><<<dim3(D_/TN, NROWS/TM, 1), 256, SMEM_DYN>>>(
        yh, yl, D_, 0, wh + 3*WW, wl + 3*WW, D_, 0, D_, 1.f, bd,
        out, nullptr, nullptr, D_, 0);
}